// round 7
// baseline (speedup 1.0000x reference)
#include <cuda_runtime.h>
#include <cstdint>

// ---------------------------------------------------------------------------
// MemoryEfficientAttnBlock on GB300 (sm_103a via compute_103)
// GroupNorm -> mma.sync(tf32) QKV -> mma.sync(tf32) flash attention
//           -> mma.sync(tf32) out proj + bias + residual
// R7: double-buffered GEMM pipelines, 128-row attention CTAs, wider gn tiles.
// ---------------------------------------------------------------------------

#define BB    4
#define CCH   512
#define HW    4096
#define NHEAD 8
#define DH    64
#define NWIN  16
#define NTOK  1024
#define TT    (NWIN * NTOK)
#define CPG   16

__device__ float g_xnT[TT * CCH];                 // normed x, [token][c]
__device__ float g_q[NWIN * NHEAD * NTOK * DH];   // [win][head][n][d]
__device__ float g_k[NWIN * NHEAD * NTOK * DH];
__device__ float g_v[NWIN * NHEAD * NTOK * DH];
__device__ float g_aoT[TT * CCH];                 // attn out, [token][head*64+d]

__device__ __forceinline__ uint32_t f2tf32(float f) {
    uint32_t r;
    asm("cvt.rna.tf32.f32 %0, %1;" : "=r"(r) : "f"(f));
    return r;
}

// D(16x8) += A(16x8,row) * B(8x8,col); tf32 in, f32 accum
__device__ __forceinline__ void mma_tf32(float* c, const uint32_t* a,
                                         const uint32_t* b) {
    asm volatile(
        "mma.sync.aligned.m16n8k8.row.col.f32.tf32.tf32.f32 "
        "{%0,%1,%2,%3}, {%4,%5,%6,%7}, {%8,%9}, {%0,%1,%2,%3};"
        : "+f"(c[0]), "+f"(c[1]), "+f"(c[2]), "+f"(c[3])
        : "r"(a[0]), "r"(a[1]), "r"(a[2]), "r"(a[3]), "r"(b[0]), "r"(b[1]));
}

// ---------------------------------------------------------------------------
// Kernel 1: GroupNorm -> token-major transpose.  grid = 128 (b,g), 256 thr.
// Transpose processes 4 h-rows per iteration (16 iters).
// ---------------------------------------------------------------------------
__global__ __launch_bounds__(256) void gn_kernel(const float* __restrict__ x,
                                                 const float* __restrict__ scale,
                                                 const float* __restrict__ bias) {
    __shared__ float rb[2][8];
    __shared__ __align__(16) float sS[4][16][68];

    int b = blockIdx.x >> 5;
    int g = blockIdx.x & 31;
    int c0 = g * CPG;
    int t = threadIdx.x;
    const float4* xp = (const float4*)(x + (size_t)(b * CCH + c0) * HW);
    const int NV = CPG * HW / 4;

    float s = 0.f, s2 = 0.f;
    for (int i = t; i < NV; i += 256) {
        float4 v = xp[i];
        s  += v.x + v.y + v.z + v.w;
        s2 += v.x * v.x + v.y * v.y + v.z * v.z + v.w * v.w;
    }
    #pragma unroll
    for (int o = 16; o; o >>= 1) {
        s  += __shfl_xor_sync(0xffffffffu, s,  o);
        s2 += __shfl_xor_sync(0xffffffffu, s2, o);
    }
    int warp = t >> 5, lane = t & 31;
    if (lane == 0) { rb[0][warp] = s; rb[1][warp] = s2; }
    __syncthreads();
    if (warp == 0) {
        s  = (lane < 8) ? rb[0][lane] : 0.f;
        s2 = (lane < 8) ? rb[1][lane] : 0.f;
        #pragma unroll
        for (int o = 4; o; o >>= 1) {
            s  += __shfl_xor_sync(0xffffffffu, s,  o);
            s2 += __shfl_xor_sync(0xffffffffu, s2, o);
        }
        if (lane == 0) { rb[0][0] = s; rb[1][0] = s2; }
    }
    __syncthreads();
    const float n = (float)(CPG * HW);
    float mu  = rb[0][0] / n;
    float var = rb[1][0] / n - mu * mu;
    float rstd = rsqrtf(var + 1e-6f);

    int cl = t >> 4, w4 = t & 15;       // load role
    float sc = scale[c0 + cl] * rstd;
    float bi = bias[c0 + cl] - mu * sc;
    int tok = t >> 2, c4 = t & 3;       // write role

    for (int hb = 0; hb < 16; hb++) {
        #pragma unroll
        for (int i = 0; i < 4; i++) {
            int h = hb * 4 + i;
            float4 v = *(const float4*)(x + (size_t)(b * CCH + c0 + cl) * HW + h * 64 + w4 * 4);
            v.x = v.x * sc + bi; v.y = v.y * sc + bi;
            v.z = v.z * sc + bi; v.w = v.w * sc + bi;
            *(float4*)&sS[i][cl][w4 * 4] = v;
        }
        __syncthreads();
        #pragma unroll
        for (int i = 0; i < 4; i++) {
            int h = hb * 4 + i;
            int win = b * 4 + (h >> 5) * 2 + (tok >> 5);
            int nn  = (h & 31) * 32 + (tok & 31);
            float4 o4 = { sS[i][c4 * 4 + 0][tok], sS[i][c4 * 4 + 1][tok],
                          sS[i][c4 * 4 + 2][tok], sS[i][c4 * 4 + 3][tok] };
            *(float4*)(g_xnT + (size_t)(win * NTOK + nn) * CCH + c0 + c4 * 4) = o4;
        }
        __syncthreads();
    }
}

// ---------------------------------------------------------------------------
// Kernel 2: QKV GEMM, mma.sync tf32, double-buffered (1 sync/chunk).
// grid = (128 n-tiles, 12 m-tiles), 256 threads (2x4 warps).
// dynamic smem: 2 stages x (A 128x36 + B 128x36) = 73728 B.
// ---------------------------------------------------------------------------
#define STG_SZ 4608          // floats per A or B stage
__global__ __launch_bounds__(256) void qkv_mma_kernel(
    const float* __restrict__ wq, const float* __restrict__ bq,
    const float* __restrict__ wk, const float* __restrict__ bk,
    const float* __restrict__ wv, const float* __restrict__ bv) {
    extern __shared__ __align__(16) float dsm[];

    int t = threadIdx.x, lane = t & 31, wid = t >> 5;
    int wrow = wid & 1, wcol = wid >> 1;
    int nt = blockIdx.x, mt = blockIdx.y;

    const float* W    = (mt < 4 ? wq : mt < 8 ? wk : wv) + (size_t)(mt & 3) * 128 * CCH;
    const float* BIAS = (mt < 4 ? bq : mt < 8 ? bk : bv);
    float* OUT        = (mt < 4 ? g_q : mt < 8 ? g_k : g_v);
    int win = nt >> 3;
    int n0  = (nt & 7) * 128;
    const float* X = g_xnT + (size_t)(win * NTOK + n0) * CCH;

    float acc[4][4][4];
    #pragma unroll
    for (int i = 0; i < 4; i++)
        #pragma unroll
        for (int j = 0; j < 4; j++)
            #pragma unroll
            for (int r = 0; r < 4; r++) acc[i][j][r] = 0.f;

    int lrow = t >> 3, lc4 = t & 7;
    int lq = lane >> 2, lr = lane & 3;

    float4 pa4[4], pb4[4];
    #pragma unroll
    for (int i = 0; i < 4; i++) {
        int row = lrow + i * 32;
        pa4[i] = *(const float4*)(W + (size_t)row * CCH + lc4 * 4);
        pb4[i] = *(const float4*)(X + (size_t)row * CCH + lc4 * 4);
    }

    for (int chunk = 0; chunk < 16; chunk++) {
        float* sA = dsm + (chunk & 1) * (2 * STG_SZ);
        float* sB = sA + STG_SZ;
        #pragma unroll
        for (int i = 0; i < 4; i++) {
            int row = lrow + i * 32;
            uint32_t* pa = (uint32_t*)&sA[row * 36 + lc4 * 4];
            uint32_t* pb = (uint32_t*)&sB[row * 36 + lc4 * 4];
            pa[0] = f2tf32(pa4[i].x); pa[1] = f2tf32(pa4[i].y);
            pa[2] = f2tf32(pa4[i].z); pa[3] = f2tf32(pa4[i].w);
            pb[0] = f2tf32(pb4[i].x); pb[1] = f2tf32(pb4[i].y);
            pb[2] = f2tf32(pb4[i].z); pb[3] = f2tf32(pb4[i].w);
        }
        if (chunk < 15) {
            int c0n = (chunk + 1) * 32;
            #pragma unroll
            for (int i = 0; i < 4; i++) {
                int row = lrow + i * 32;
                pa4[i] = *(const float4*)(W + (size_t)row * CCH + c0n + lc4 * 4);
                pb4[i] = *(const float4*)(X + (size_t)row * CCH + c0n + lc4 * 4);
            }
        }
        __syncthreads();
        #pragma unroll
        for (int ks = 0; ks < 4; ks++) {
            int k0 = ks * 8;
            uint32_t af[4][4], bf[4][2];
            #pragma unroll
            for (int mi = 0; mi < 4; mi++) {
                int m = wrow * 64 + mi * 16 + lq;
                af[mi][0] = __float_as_uint(sA[m * 36 + k0 + lr]);
                af[mi][1] = __float_as_uint(sA[(m + 8) * 36 + k0 + lr]);
                af[mi][2] = __float_as_uint(sA[m * 36 + k0 + lr + 4]);
                af[mi][3] = __float_as_uint(sA[(m + 8) * 36 + k0 + lr + 4]);
            }
            #pragma unroll
            for (int ni = 0; ni < 4; ni++) {
                int nn = wcol * 32 + ni * 8 + lq;
                bf[ni][0] = __float_as_uint(sB[nn * 36 + k0 + lr]);
                bf[ni][1] = __float_as_uint(sB[nn * 36 + k0 + lr + 4]);
            }
            #pragma unroll
            for (int mi = 0; mi < 4; mi++)
                #pragma unroll
                for (int ni = 0; ni < 4; ni++)
                    mma_tf32(acc[mi][ni], af[mi], bf[ni]);
        }
    }
    __syncthreads();

    float* sT = dsm;   // [32 n][132 o]
    int o0c = (mt & 3) * 128;
    for (int cb = 0; cb < 4; cb++) {
        if (wcol == cb) {
            #pragma unroll
            for (int mi = 0; mi < 4; mi++) {
                int ob = wrow * 64 + mi * 16 + lq;
                #pragma unroll
                for (int ni = 0; ni < 4; ni++) {
                    int nb = ni * 8 + 2 * lr;
                    sT[nb * 132 + ob]           = acc[mi][ni][0];
                    sT[(nb + 1) * 132 + ob]     = acc[mi][ni][1];
                    sT[nb * 132 + ob + 8]       = acc[mi][ni][2];
                    sT[(nb + 1) * 132 + ob + 8] = acc[mi][ni][3];
                }
            }
        }
        __syncthreads();
        for (int idx = t; idx < 1024; idx += 256) {
            int nn = idx >> 5, of4 = (idx & 31) * 4;
            int ochan = o0c + of4;
            int head = ochan >> 6, d = ochan & 63;
            float4 v = *(const float4*)&sT[nn * 132 + of4];
            float4 bb = *(const float4*)&BIAS[ochan];
            v.x += bb.x; v.y += bb.y; v.z += bb.z; v.w += bb.w;
            size_t ga = ((size_t)(win * NHEAD + head) * NTOK + n0 + cb * 32 + nn) * DH + d;
            *(float4*)(OUT + ga) = v;
        }
        __syncthreads();
    }
}

// ---------------------------------------------------------------------------
// Kernel 3: flash attention on mma.sync tf32.
// grid = (8 q-tiles, 8 heads, 16 windows), 256 threads (8 warps x 16 q-rows).
// 128 q-rows per CTA; K/V tiles of 64 rows staged as tf32 bits in smem.
// ---------------------------------------------------------------------------
__global__ __launch_bounds__(256) void attn_mma_kernel() {
    __shared__ __align__(16) float sbuf[2 * 64 * 72];
    float* sK = sbuf;
    float* sV = sbuf + 64 * 72;

    int qt = blockIdx.x, head = blockIdx.y, win = blockIdx.z;
    int t = threadIdx.x, lane = t & 31, wid = t >> 5;
    int lq = lane >> 2, lr = lane & 3;
    int q0w = wid * 16;

    size_t hb = ((size_t)win * NHEAD + head) * NTOK * DH;
    const float* Qg = g_q + hb + (size_t)(qt * 128) * DH;

    // build persistent Q A-fragments in two 64-row passes through sK
    uint32_t qa[8][4];
    #pragma unroll
    for (int half = 0; half < 2; half++) {
        for (int idx = t; idx < 1024; idx += 256) {
            int r = idx >> 4, c4 = idx & 15;
            float4 v = *(const float4*)(Qg + (size_t)(half * 64 + r) * DH + c4 * 4);
            v.x *= 0.125f; v.y *= 0.125f; v.z *= 0.125f; v.w *= 0.125f;
            *(float4*)&sK[r * 72 + c4 * 4] = v;
        }
        __syncthreads();
        if ((wid >> 2) == half) {
            int r0 = (q0w & 63) + lq;
            #pragma unroll
            for (int j = 0; j < 8; j++) {
                qa[j][0] = f2tf32(sK[r0 * 72 + j * 8 + lr]);
                qa[j][1] = f2tf32(sK[(r0 + 8) * 72 + j * 8 + lr]);
                qa[j][2] = f2tf32(sK[r0 * 72 + j * 8 + lr + 4]);
                qa[j][3] = f2tf32(sK[(r0 + 8) * 72 + j * 8 + lr + 4]);
            }
        }
        __syncthreads();
    }

    float m0 = -1e30f, m1 = -1e30f, l0 = 0.f, l1 = 0.f;
    float oa[8][4];
    #pragma unroll
    for (int nv = 0; nv < 8; nv++)
        #pragma unroll
        for (int r = 0; r < 4; r++) oa[nv][r] = 0.f;

    for (int kt = 0; kt < 16; kt++) {
        const float* Kg = g_k + hb + (size_t)(kt * 64) * DH;
        const float* Vg = g_v + hb + (size_t)(kt * 64) * DH;
        for (int idx = t; idx < 1024; idx += 256) {
            int r = idx >> 4, c4 = idx & 15;
            float4 k4 = *(const float4*)(Kg + (size_t)r * DH + c4 * 4);
            float4 v4 = *(const float4*)(Vg + (size_t)r * DH + c4 * 4);
            uint32_t* pk = (uint32_t*)&sK[r * 72 + c4 * 4];
            uint32_t* pv = (uint32_t*)&sV[r * 72 + c4 * 4];
            pk[0] = f2tf32(k4.x); pk[1] = f2tf32(k4.y);
            pk[2] = f2tf32(k4.z); pk[3] = f2tf32(k4.w);
            pv[0] = f2tf32(v4.x); pv[1] = f2tf32(v4.y);
            pv[2] = f2tf32(v4.z); pv[3] = f2tf32(v4.w);
        }
        __syncthreads();

        // S = Q K^T  (64 k-cols)
        float sc[8][4];
        #pragma unroll
        for (int nj = 0; nj < 8; nj++)
            #pragma unroll
            for (int r = 0; r < 4; r++) sc[nj][r] = 0.f;
        #pragma unroll
        for (int j2 = 0; j2 < 8; j2++) {
            #pragma unroll
            for (int nj = 0; nj < 8; nj++) {
                uint32_t b[2];
                b[0] = __float_as_uint(sK[(nj * 8 + lq) * 72 + j2 * 8 + lr]);
                b[1] = __float_as_uint(sK[(nj * 8 + lq) * 72 + j2 * 8 + lr + 4]);
                mma_tf32(sc[nj], qa[j2], b);
            }
        }

        // online softmax
        float mx0 = -1e30f, mx1 = -1e30f;
        #pragma unroll
        for (int nj = 0; nj < 8; nj++) {
            mx0 = fmaxf(mx0, fmaxf(sc[nj][0], sc[nj][1]));
            mx1 = fmaxf(mx1, fmaxf(sc[nj][2], sc[nj][3]));
        }
        mx0 = fmaxf(mx0, __shfl_xor_sync(0xffffffffu, mx0, 1));
        mx0 = fmaxf(mx0, __shfl_xor_sync(0xffffffffu, mx0, 2));
        mx1 = fmaxf(mx1, __shfl_xor_sync(0xffffffffu, mx1, 1));
        mx1 = fmaxf(mx1, __shfl_xor_sync(0xffffffffu, mx1, 2));
        float mn0 = fmaxf(m0, mx0), mn1 = fmaxf(m1, mx1);
        float s0 = 0.f, s1 = 0.f;
        #pragma unroll
        for (int nj = 0; nj < 8; nj++) {
            sc[nj][0] = __expf(sc[nj][0] - mn0); s0 += sc[nj][0];
            sc[nj][1] = __expf(sc[nj][1] - mn0); s0 += sc[nj][1];
            sc[nj][2] = __expf(sc[nj][2] - mn1); s1 += sc[nj][2];
            sc[nj][3] = __expf(sc[nj][3] - mn1); s1 += sc[nj][3];
        }
        s0 += __shfl_xor_sync(0xffffffffu, s0, 1);
        s0 += __shfl_xor_sync(0xffffffffu, s0, 2);
        s1 += __shfl_xor_sync(0xffffffffu, s1, 1);
        s1 += __shfl_xor_sync(0xffffffffu, s1, 2);
        float al0 = __expf(m0 - mn0), al1 = __expf(m1 - mn1);
        l0 = l0 * al0 + s0; l1 = l1 * al1 + s1;
        m0 = mn0; m1 = mn1;
        #pragma unroll
        for (int nv = 0; nv < 8; nv++) {
            oa[nv][0] *= al0; oa[nv][1] *= al0;
            oa[nv][2] *= al1; oa[nv][3] *= al1;
        }

        // O += P V : quad-shuffle C-frag -> A-frag, mma over d-blocks
        #pragma unroll
        for (int j = 0; j < 8; j++) {
            int src0 = (lane & ~3) | (lr >> 1);
            int src1 = src0 + 2;
            float v00 = __shfl_sync(0xffffffffu, sc[j][0], src0);
            float v01 = __shfl_sync(0xffffffffu, sc[j][1], src0);
            float v10 = __shfl_sync(0xffffffffu, sc[j][2], src0);
            float v11 = __shfl_sync(0xffffffffu, sc[j][3], src0);
            float w00 = __shfl_sync(0xffffffffu, sc[j][0], src1);
            float w01 = __shfl_sync(0xffffffffu, sc[j][1], src1);
            float w10 = __shfl_sync(0xffffffffu, sc[j][2], src1);
            float w11 = __shfl_sync(0xffffffffu, sc[j][3], src1);
            bool odd = (lr & 1);
            uint32_t pa[4];
            pa[0] = f2tf32(odd ? v01 : v00);
            pa[1] = f2tf32(odd ? v11 : v10);
            pa[2] = f2tf32(odd ? w01 : w00);
            pa[3] = f2tf32(odd ? w11 : w10);
            #pragma unroll
            for (int nv = 0; nv < 8; nv++) {
                uint32_t b[2];
                b[0] = __float_as_uint(sV[(j * 8 + lr) * 72 + nv * 8 + lq]);
                b[1] = __float_as_uint(sV[(j * 8 + lr + 4) * 72 + nv * 8 + lq]);
                mma_tf32(oa[nv], pa, b);
            }
        }
        __syncthreads();
    }

    // finalize + stage [128][65] + token-major write
    float inv0 = 1.f / l0, inv1 = 1.f / l1;
    float* sOut = sbuf;
    #pragma unroll
    for (int nv = 0; nv < 8; nv++) {
        sOut[(q0w + lq) * 65 + nv * 8 + 2 * lr]         = oa[nv][0] * inv0;
        sOut[(q0w + lq) * 65 + nv * 8 + 2 * lr + 1]     = oa[nv][1] * inv0;
        sOut[(q0w + lq + 8) * 65 + nv * 8 + 2 * lr]     = oa[nv][2] * inv1;
        sOut[(q0w + lq + 8) * 65 + nv * 8 + 2 * lr + 1] = oa[nv][3] * inv1;
    }
    __syncthreads();
    size_t tb = ((size_t)win * NTOK + qt * 128) * CCH + head * DH;
    for (int idx = t; idx < 8192; idx += 256) {
        int r = idx >> 6, d = idx & 63;
        g_aoT[tb + (size_t)r * CCH + d] = sOut[r * 65 + d];
    }
}

// ---------------------------------------------------------------------------
// Kernel 4: out projection, mma.sync tf32, double-buffered + bias + residual.
// grid = (128 n-tiles, 4 m-tiles), 256 threads. dynamic smem 73728 B.
// ---------------------------------------------------------------------------
__global__ __launch_bounds__(256) void oproj_mma_kernel(
    const float* __restrict__ x, const float* __restrict__ wo,
    const float* __restrict__ bo, float* __restrict__ out) {
    extern __shared__ __align__(16) float dsm[];

    int t = threadIdx.x, lane = t & 31, wid = t >> 5;
    int wrow = wid & 1, wcol = wid >> 1;
    int nt = blockIdx.x, mt = blockIdx.y;

    int o0  = mt * 128;
    int win = nt >> 3;
    int n0  = (nt & 7) * 128;
    int b   = win >> 2, wh = (win >> 1) & 1, ww = win & 1;
    const float* W = wo + (size_t)o0 * CCH;
    const float* X = g_aoT + (size_t)(win * NTOK + n0) * CCH;

    float acc[4][4][4];
    #pragma unroll
    for (int i = 0; i < 4; i++)
        #pragma unroll
        for (int j = 0; j < 4; j++)
            #pragma unroll
            for (int r = 0; r < 4; r++) acc[i][j][r] = 0.f;

    int lrow = t >> 3, lc4 = t & 7;
    int lq = lane >> 2, lr = lane & 3;

    float4 pa4[4], pb4[4];
    #pragma unroll
    for (int i = 0; i < 4; i++) {
        int row = lrow + i * 32;
        pa4[i] = *(const float4*)(W + (size_t)row * CCH + lc4 * 4);
        pb4[i] = *(const float4*)(X + (size_t)row * CCH + lc4 * 4);
    }

    for (int chunk = 0; chunk < 16; chunk++) {
        float* sA = dsm + (chunk & 1) * (2 * STG_SZ);
        float* sB = sA + STG_SZ;
        #pragma unroll
        for (int i = 0; i < 4; i++) {
            int row = lrow + i * 32;
            uint32_t* pa = (uint32_t*)&sA[row * 36 + lc4 * 4];
            uint32_t* pb = (uint32_t*)&sB[row * 36 + lc4 * 4];
            pa[0] = f2tf32(pa4[i].x); pa[1] = f2tf32(pa4[i].y);
            pa[2] = f2tf32(pa4[i].z); pa[3] = f2tf32(pa4[i].w);
            pb[0] = f2tf32(pb4[i].x); pb[1] = f2tf32(pb4[i].y);
            pb[2] = f2tf32(pb4[i].z); pb[3] = f2tf32(pb4[i].w);
        }
        if (chunk < 15) {
            int c0n = (chunk + 1) * 32;
            #pragma unroll
            for (int i = 0; i < 4; i++) {
                int row = lrow + i * 32;
                pa4[i] = *(const float4*)(W + (size_t)row * CCH + c0n + lc4 * 4);
                pb4[i] = *(const float4*)(X + (size_t)row * CCH + c0n + lc4 * 4);
            }
        }
        __syncthreads();
        #pragma unroll
        for (int ks = 0; ks < 4; ks++) {
            int k0 = ks * 8;
            uint32_t af[4][4], bf[4][2];
            #pragma unroll
            for (int mi = 0; mi < 4; mi++) {
                int m = wrow * 64 + mi * 16 + lq;
                af[mi][0] = __float_as_uint(sA[m * 36 + k0 + lr]);
                af[mi][1] = __float_as_uint(sA[(m + 8) * 36 + k0 + lr]);
                af[mi][2] = __float_as_uint(sA[m * 36 + k0 + lr + 4]);
                af[mi][3] = __float_as_uint(sA[(m + 8) * 36 + k0 + lr + 4]);
            }
            #pragma unroll
            for (int ni = 0; ni < 4; ni++) {
                int nn = wcol * 32 + ni * 8 + lq;
                bf[ni][0] = __float_as_uint(sB[nn * 36 + k0 + lr]);
                bf[ni][1] = __float_as_uint(sB[nn * 36 + k0 + lr + 4]);
            }
            #pragma unroll
            for (int mi = 0; mi < 4; mi++)
                #pragma unroll
                for (int ni = 0; ni < 4; ni++)
                    mma_tf32(acc[mi][ni], af[mi], bf[ni]);
        }
    }
    __syncthreads();

    float* sT = dsm;   // [128 o][36]
    for (int cb = 0; cb < 4; cb++) {
        if (wcol == cb) {
            #pragma unroll
            for (int mi = 0; mi < 4; mi++) {
                int ob = wrow * 64 + mi * 16 + lq;
                #pragma unroll
                for (int ni = 0; ni < 4; ni++) {
                    int nb = ni * 8 + 2 * lr;
                    sT[ob * 36 + nb]           = acc[mi][ni][0];
                    sT[ob * 36 + nb + 1]       = acc[mi][ni][1];
                    sT[(ob + 8) * 36 + nb]     = acc[mi][ni][2];
                    sT[(ob + 8) * 36 + nb + 1] = acc[mi][ni][3];
                }
            }
        }
        __syncthreads();

        int nb = n0 + cb * 32;
        int w1 = nb >> 5;
        int h  = wh * 32 + (w1 & 31);
        for (int idx = t; idx < 1024; idx += 256) {
            int o = idx >> 3, f4 = idx & 7;
            float4 v = *(const float4*)&sT[o * 36 + f4 * 4];
            float bval = bo[o0 + o];
            size_t ga = ((size_t)(b * CCH + o0 + o) * HW) + h * 64 + ww * 32 + f4 * 4;
            float4 xr = *(const float4*)(x + ga);
            v.x += bval + xr.x; v.y += bval + xr.y;
            v.z += bval + xr.z; v.w += bval + xr.w;
            *(float4*)(out + ga) = v;
        }
        __syncthreads();
    }
}

// ---------------------------------------------------------------------------
extern "C" void kernel_launch(void* const* d_in, const int* in_sizes, int n_in,
                              void* d_out, int out_size) {
    (void)in_sizes; (void)n_in; (void)out_size;
    const float* x  = (const float*)d_in[0];
    const float* ns = (const float*)d_in[1];
    const float* nb = (const float*)d_in[2];
    const float* wq = (const float*)d_in[3];
    const float* bq = (const float*)d_in[4];
    const float* wk = (const float*)d_in[5];
    const float* bk = (const float*)d_in[6];
    const float* wv = (const float*)d_in[7];
    const float* bv = (const float*)d_in[8];
    const float* wo = (const float*)d_in[9];
    const float* bo = (const float*)d_in[10];
    float* out = (float*)d_out;

    const int GEMM_SMEM = 4 * STG_SZ * (int)sizeof(float);   // 73728
    cudaFuncSetAttribute(qkv_mma_kernel,
                         cudaFuncAttributeMaxDynamicSharedMemorySize, GEMM_SMEM);
    cudaFuncSetAttribute(oproj_mma_kernel,
                         cudaFuncAttributeMaxDynamicSharedMemorySize, GEMM_SMEM);

    gn_kernel<<<128, 256>>>(x, ns, nb);
    qkv_mma_kernel<<<dim3(128, 12), 256, GEMM_SMEM>>>(wq, bq, wk, bk, wv, bv);
    attn_mma_kernel<<<dim3(8, 8, 16), 256>>>();
    oproj_mma_kernel<<<dim3(128, 4), 256, GEMM_SMEM>>>(x, wo, bo, out);
}